// round 9
// baseline (speedup 1.0000x reference)
#include <cuda_runtime.h>

#define N_SYM 128
#define LEVERAGE 30.0f
#define ST 8            // cp.async pipeline stages
#define TPB 256         // threads per block

// smem staging: [ST][4 arrays][TPB] float2 = ST*8KB
#define STAGE_BYTES (4 * TPB * 8)

__device__ __forceinline__ void cp_async8(unsigned smem_addr, const void* gptr) {
    asm volatile("cp.async.ca.shared.global [%0], [%1], 8;\n"
                 :: "r"(smem_addr), "l"(gptr) : "memory");
}
__device__ __forceinline__ void cp_commit() {
    asm volatile("cp.async.commit_group;\n" ::: "memory");
}
template <int N>
__device__ __forceinline__ void cp_wait() {
    asm volatile("cp.async.wait_group %0;\n" :: "n"(N) : "memory");
}

__device__ __forceinline__ float step1(float f, float e, float p, float m,
                                       float um, float st, float rst,
                                       float mn, float mx, float& um_out)
{
    float tm  = m * LEVERAGE;
    float us  = um * tm;
    float mps = fabsf(p) + us;
    float adj = fminf((p * f > 0.0f) ? us : mps, 0.0f);
    float nps = f * (mps - adj);
    float an  = fabsf(nps);
    an = floorf(an * rst) * st;
    an = (an < mn) ? 0.0f : an;
    an = fminf(an, mx);
    um_out = __fdividef(mps - an, tm);
    return (e > 0.5f) ? copysignf(an, nps) : p;
}

__global__ void __launch_bounds__(TPB)
lowlevel_scan_kernel(
    const float2* __restrict__ F,   // [N_SYM, B2]
    const float2* __restrict__ E,
    const float2* __restrict__ P,
    const float2* __restrict__ M,
    const float2* __restrict__ UM,  // [B2]
    const float*  __restrict__ msm_min,
    const float*  __restrict__ msm_step,
    const float*  __restrict__ msm_max,
    float2* __restrict__ out_nps,   // [N_SYM, B2]
    float2* __restrict__ out_um,    // [B2] or nullptr
    int B2)
{
    __shared__ float s_mn[N_SYM];
    __shared__ float s_st[N_SYM];
    __shared__ float s_rst[N_SYM];
    __shared__ float s_mx[N_SYM];
    extern __shared__ float2 stg[];   // [ST][4][TPB]

    int t = threadIdx.x;
    if (t < N_SYM) {
        float st = msm_step[t];
        s_st[t]  = st;
        s_rst[t] = 1.0f / st;
        s_mn[t]  = msm_min[t];
        s_mx[t]  = msm_max[t];
    }
    // no __syncthreads needed before table use until first compute below;
    // but keep one for safety of the tables (cheap, outside the loop)
    __syncthreads();

    int c = blockIdx.x * blockDim.x + t;
    if (c >= B2) return;

    // per-thread smem staging addresses (u32 shared-space)
    unsigned sbase;
    asm("{ .reg .u64 u; cvta.to.shared.u64 u, %1; cvt.u32.u64 %0, u; }"
        : "=r"(sbase) : "l"(stg + t));
    // slot(stage, arr) = sbase + (stage*4 + arr)*TPB*8

    float2 um = UM[c];

    // prologue: fill ST stages
#pragma unroll
    for (int i = 0; i < ST; ++i) {
        int id = i * B2 + c;
        unsigned a = sbase + (unsigned)(i * 4) * (TPB * 8);
        cp_async8(a + 0 * TPB * 8, F + id);
        cp_async8(a + 1 * TPB * 8, E + id);
        cp_async8(a + 2 * TPB * 8, P + id);
        cp_async8(a + 3 * TPB * 8, M + id);
        cp_commit();
    }

#pragma unroll 4
    for (int s = 0; s < N_SYM; ++s) {
        cp_wait<ST - 1>();   // stage s resident

        int j = s & (ST - 1);
        const float2* slot = stg + (j * 4) * TPB + t;
        float2 f = slot[0 * TPB];
        float2 e = slot[1 * TPB];
        float2 p = slot[2 * TPB];
        float2 m = slot[3 * TPB];

        // refill slot j with row s+ST (consumed values already in registers)
        if (s + ST < N_SYM) {
            int id = (s + ST) * B2 + c;
            unsigned a = sbase + (unsigned)(j * 4) * (TPB * 8);
            cp_async8(a + 0 * TPB * 8, F + id);
            cp_async8(a + 1 * TPB * 8, E + id);
            cp_async8(a + 2 * TPB * 8, P + id);
            cp_async8(a + 3 * TPB * 8, M + id);
        }
        cp_commit();   // commit every iter (possibly empty) to keep group count fixed

        float st = s_st[s], rst = s_rst[s], mn = s_mn[s], mx = s_mx[s];

        float2 o;
        o.x = step1(f.x, e.x, p.x, m.x, um.x, st, rst, mn, mx, um.x);
        o.y = step1(f.y, e.y, p.y, m.y, um.y, st, rst, mn, mx, um.y);
        out_nps[s * B2 + c] = o;
    }

    if (out_um != nullptr) out_um[c] = um;
}

extern "C" void kernel_launch(void* const* d_in, const int* in_sizes, int n_in,
                              void* d_out, int out_size)
{
    const float* fractions     = (const float*)d_in[0];
    const float* exec_samples  = (const float*)d_in[1];
    const float* pos_sizes     = (const float*)d_in[2];
    const float* margin_rates  = (const float*)d_in[3];
    const float* unused_margin = (const float*)d_in[4];
    const float* msm_min       = (const float*)d_in[5];
    const float* msm_step      = (const float*)d_in[6];
    const float* msm_max       = (const float*)d_in[7];

    int B  = in_sizes[4];     // BATCH
    int B2 = B / 2;           // float2 columns

    float* out_nps = (float*)d_out;
    float* out_um  = nullptr;
    if ((long long)out_size >= (long long)N_SYM * B + B)
        out_um = out_nps + (size_t)N_SYM * B;

    int dyn_smem = ST * STAGE_BYTES;   // 64 KB
    static int attr_set = 0;
    if (!attr_set) {
        cudaFuncSetAttribute(lowlevel_scan_kernel,
                             cudaFuncAttributeMaxDynamicSharedMemorySize, dyn_smem);
        attr_set = 1;
    }

    int threads = TPB;
    int blocks  = (B2 + threads - 1) / threads;   // 256 CTAs for B=131072
    lowlevel_scan_kernel<<<blocks, threads, dyn_smem>>>(
        (const float2*)fractions, (const float2*)exec_samples,
        (const float2*)pos_sizes, (const float2*)margin_rates,
        (const float2*)unused_margin,
        msm_min, msm_step, msm_max,
        (float2*)out_nps, (float2*)out_um, B2);
}

// round 10
// speedup vs baseline: 1.2013x; 1.2013x over previous
#include <cuda_runtime.h>

#define N_SYM 128
#define LEVERAGE 30.0f
#define PF 4   // prefetch depth (iterations of load buffers in flight)

__device__ __forceinline__ float step1(float f, float e, float p, float m,
                                       float um, float st, float rst,
                                       float mn, float mx, float& um_out)
{
    float tm  = m * LEVERAGE;
    float us  = um * tm;
    float mps = fabsf(p) + us;
    float adj = fminf((p * f > 0.0f) ? us : mps, 0.0f);
    float nps = f * (mps - adj);
    float an  = fabsf(nps);
    an = floorf(an * rst) * st;
    an = (an < mn) ? 0.0f : an;
    an = fminf(an, mx);
    um_out = __fdividef(mps - an, tm);
    return (e > 0.5f) ? copysignf(an, nps) : p;
}

__global__ void __launch_bounds__(256)
lowlevel_scan_kernel(
    const float2* __restrict__ F,   // [N_SYM, B2]
    const float2* __restrict__ E,
    const float2* __restrict__ P,
    const float2* __restrict__ M,
    const float2* __restrict__ UM,  // [B2]
    const float*  __restrict__ msm_min,
    const float*  __restrict__ msm_step,
    const float*  __restrict__ msm_max,
    float2* __restrict__ out_nps,   // [N_SYM, B2]
    float2* __restrict__ out_um,    // [B2] or nullptr
    int B2)
{
    __shared__ float s_mn[N_SYM];
    __shared__ float s_st[N_SYM];
    __shared__ float s_rst[N_SYM];
    __shared__ float s_mx[N_SYM];

    int t = threadIdx.x;
    if (t < N_SYM) {
        float st = msm_step[t];
        s_st[t]  = st;
        s_rst[t] = 1.0f / st;
        s_mn[t]  = msm_min[t];
        s_mx[t]  = msm_max[t];
    }
    __syncthreads();

    int c = blockIdx.x * blockDim.x + t;
    if (c >= B2) return;

    float2 um = UM[c];

    // Rotating register buffers: PF iterations of loads in flight.
    float2 bf[PF], be[PF], bp[PF], bm[PF];
#pragma unroll
    for (int i = 0; i < PF; ++i) {
        int id = i * B2 + c;
        bf[i] = F[id]; be[i] = E[id]; bp[i] = P[id]; bm[i] = M[id];
    }

#pragma unroll 4
    for (int s = 0; s < N_SYM; ++s) {
        int j = s & (PF - 1);
        float2 f = bf[j], e = be[j], p = bp[j], m = bm[j];

        // refill buffer slot j with iteration s+PF (issued early, overlaps compute)
        if (s + PF < N_SYM) {
            int id = (s + PF) * B2 + c;
            bf[j] = F[id]; be[j] = E[id]; bp[j] = P[id]; bm[j] = M[id];
        }

        float st = s_st[s], rst = s_rst[s], mn = s_mn[s], mx = s_mx[s];

        float2 o;
        o.x = step1(f.x, e.x, p.x, m.x, um.x, st, rst, mn, mx, um.x);
        o.y = step1(f.y, e.y, p.y, m.y, um.y, st, rst, mn, mx, um.y);
        __stcs(&out_nps[s * B2 + c], o);   // evict-first: prompt, in-order writeback
    }

    if (out_um != nullptr) __stcs(&out_um[c], um);
}

extern "C" void kernel_launch(void* const* d_in, const int* in_sizes, int n_in,
                              void* d_out, int out_size)
{
    const float* fractions     = (const float*)d_in[0];
    const float* exec_samples  = (const float*)d_in[1];
    const float* pos_sizes     = (const float*)d_in[2];
    const float* margin_rates  = (const float*)d_in[3];
    const float* unused_margin = (const float*)d_in[4];
    const float* msm_min       = (const float*)d_in[5];
    const float* msm_step      = (const float*)d_in[6];
    const float* msm_max       = (const float*)d_in[7];

    int B  = in_sizes[4];     // BATCH
    int B2 = B / 2;           // float2 columns

    float* out_nps = (float*)d_out;
    float* out_um  = nullptr;
    if ((long long)out_size >= (long long)N_SYM * B + B)
        out_um = out_nps + (size_t)N_SYM * B;

    int threads = 256;
    int blocks  = (B2 + threads - 1) / threads;   // 256 CTAs for B=131072
    lowlevel_scan_kernel<<<blocks, threads>>>(
        (const float2*)fractions, (const float2*)exec_samples,
        (const float2*)pos_sizes, (const float2*)margin_rates,
        (const float2*)unused_margin,
        msm_min, msm_step, msm_max,
        (float2*)out_nps, (float2*)out_um, B2);
}

// round 11
// speedup vs baseline: 1.2019x; 1.0005x over previous
#include <cuda_runtime.h>

#define N_SYM 128
#define LEVERAGE 30.0f
#define PF 4   // prefetch depth (iterations of load buffers in flight)

__device__ __forceinline__ float step1(float f, float e, float p, float m,
                                       float um, float st, float rst,
                                       float mn, float mx, float& um_out)
{
    float tm  = m * LEVERAGE;
    float us  = um * tm;
    float mps = fabsf(p) + us;
    float adj = fminf((p * f > 0.0f) ? us : mps, 0.0f);
    float nps = f * (mps - adj);
    float an  = fabsf(nps);
    an = floorf(an * rst) * st;
    an = (an < mn) ? 0.0f : an;
    an = fminf(an, mx);
    um_out = __fdividef(mps - an, tm);
    return (e > 0.5f) ? copysignf(an, nps) : p;
}

__global__ void __launch_bounds__(256)
lowlevel_scan_kernel(
    const float2* __restrict__ F,   // [N_SYM, B2]
    const float2* __restrict__ E,
    const float2* __restrict__ P,
    const float2* __restrict__ M,
    const float2* __restrict__ UM,  // [B2]
    const float*  __restrict__ msm_min,
    const float*  __restrict__ msm_step,
    const float*  __restrict__ msm_max,
    float2* __restrict__ out_nps,   // [N_SYM, B2]
    float2* __restrict__ out_um,    // [B2] or nullptr
    int B2)
{
    __shared__ float s_mn[N_SYM];
    __shared__ float s_st[N_SYM];
    __shared__ float s_rst[N_SYM];
    __shared__ float s_mx[N_SYM];

    int t = threadIdx.x;
    if (t < N_SYM) {
        float st = msm_step[t];
        s_st[t]  = st;
        s_rst[t] = 1.0f / st;
        s_mn[t]  = msm_min[t];
        s_mx[t]  = msm_max[t];
    }
    __syncthreads();

    int c = blockIdx.x * blockDim.x + t;
    if (c >= B2) return;

    float2 um = UM[c];

    // Rotating register buffers: PF iterations of loads in flight.
    // All reads evict-first: lines are dead immediately after consumption.
    float2 bf[PF], be[PF], bp[PF], bm[PF];
#pragma unroll
    for (int i = 0; i < PF; ++i) {
        int id = i * B2 + c;
        bf[i] = __ldcs(&F[id]); be[i] = __ldcs(&E[id]);
        bp[i] = __ldcs(&P[id]); bm[i] = __ldcs(&M[id]);
    }

#pragma unroll 4
    for (int s = 0; s < N_SYM; ++s) {
        int j = s & (PF - 1);
        float2 f = bf[j], e = be[j], p = bp[j], m = bm[j];

        // refill buffer slot j with iteration s+PF (issued early, overlaps compute)
        if (s + PF < N_SYM) {
            int id = (s + PF) * B2 + c;
            bf[j] = __ldcs(&F[id]); be[j] = __ldcs(&E[id]);
            bp[j] = __ldcs(&P[id]); bm[j] = __ldcs(&M[id]);
        }

        float st = s_st[s], rst = s_rst[s], mn = s_mn[s], mx = s_mx[s];

        float2 o;
        o.x = step1(f.x, e.x, p.x, m.x, um.x, st, rst, mn, mx, um.x);
        o.y = step1(f.y, e.y, p.y, m.y, um.y, st, rst, mn, mx, um.y);
        __stcs(&out_nps[s * B2 + c], o);   // evict-first writeback
    }

    if (out_um != nullptr) __stcs(&out_um[c], um);
}

extern "C" void kernel_launch(void* const* d_in, const int* in_sizes, int n_in,
                              void* d_out, int out_size)
{
    const float* fractions     = (const float*)d_in[0];
    const float* exec_samples  = (const float*)d_in[1];
    const float* pos_sizes     = (const float*)d_in[2];
    const float* margin_rates  = (const float*)d_in[3];
    const float* unused_margin = (const float*)d_in[4];
    const float* msm_min       = (const float*)d_in[5];
    const float* msm_step      = (const float*)d_in[6];
    const float* msm_max       = (const float*)d_in[7];

    int B  = in_sizes[4];     // BATCH
    int B2 = B / 2;           // float2 columns

    float* out_nps = (float*)d_out;
    float* out_um  = nullptr;
    if ((long long)out_size >= (long long)N_SYM * B + B)
        out_um = out_nps + (size_t)N_SYM * B;

    int threads = 256;
    int blocks  = (B2 + threads - 1) / threads;   // 256 CTAs for B=131072
    lowlevel_scan_kernel<<<blocks, threads>>>(
        (const float2*)fractions, (const float2*)exec_samples,
        (const float2*)pos_sizes, (const float2*)margin_rates,
        (const float2*)unused_margin,
        msm_min, msm_step, msm_max,
        (float2*)out_nps, (float2*)out_um, B2);
}

// round 12
// speedup vs baseline: 1.2291x; 1.0226x over previous
#include <cuda_runtime.h>

#define N_SYM 128
#define LEVERAGE 30.0f
#define PF 4   // prefetch depth (iterations of load buffers in flight)

__device__ __forceinline__ float step1(float f, float e, float p, float m,
                                       float um, float st, float rst,
                                       float mn, float mx, float& um_out)
{
    float tm  = m * LEVERAGE;
    float us  = um * tm;
    float mps = fabsf(p) + us;
    float adj = fminf((p * f > 0.0f) ? us : mps, 0.0f);
    float nps = f * (mps - adj);
    float an  = fabsf(nps);
    an = floorf(an * rst) * st;
    an = (an < mn) ? 0.0f : an;
    an = fminf(an, mx);
    um_out = __fdividef(mps - an, tm);
    return (e > 0.5f) ? copysignf(an, nps) : p;
}

__global__ void __launch_bounds__(256)
lowlevel_scan_kernel(
    const float2* __restrict__ F,   // [N_SYM, B2]
    const float2* __restrict__ E,
    const float2* __restrict__ P,
    const float2* __restrict__ M,
    const float2* __restrict__ UM,  // [B2]
    const float*  __restrict__ msm_min,
    const float*  __restrict__ msm_step,
    const float*  __restrict__ msm_max,
    float2* __restrict__ out_nps,   // [N_SYM, B2]
    float2* __restrict__ out_um,    // [B2] or nullptr
    int B2)
{
    __shared__ float s_mn[N_SYM];
    __shared__ float s_st[N_SYM];
    __shared__ float s_rst[N_SYM];
    __shared__ float s_mx[N_SYM];

    int t = threadIdx.x;
    if (t < N_SYM) {
        float st = msm_step[t];
        s_st[t]  = st;
        s_rst[t] = 1.0f / st;
        s_mn[t]  = msm_min[t];
        s_mx[t]  = msm_max[t];
    }
    __syncthreads();

    int c = blockIdx.x * blockDim.x + t;
    if (c >= B2) return;

    float2 um = UM[c];

    // Rotating register buffers: PF iterations of loads in flight.
    // Reads evict-first: lines are dead immediately after consumption.
    float2 bf[PF], be[PF], bp[PF], bm[PF];
#pragma unroll
    for (int i = 0; i < PF; ++i) {
        int id = i * B2 + c;
        bf[i] = __ldcs(&F[id]); be[i] = __ldcs(&E[id]);
        bp[i] = __ldcs(&P[id]); bm[i] = __ldcs(&M[id]);
    }

#pragma unroll 4
    for (int s = 0; s < N_SYM; ++s) {
        int j = s & (PF - 1);
        float2 f = bf[j], e = be[j], p = bp[j], m = bm[j];

        // refill buffer slot j with iteration s+PF (issued early, overlaps compute)
        if (s + PF < N_SYM) {
            int id = (s + PF) * B2 + c;
            bf[j] = __ldcs(&F[id]); be[j] = __ldcs(&E[id]);
            bp[j] = __ldcs(&P[id]); bm[j] = __ldcs(&M[id]);
        }

        float st = s_st[s], rst = s_rst[s], mn = s_mn[s], mx = s_mx[s];

        float2 o;
        o.x = step1(f.x, e.x, p.x, m.x, um.x, st, rst, mn, mx, um.x);
        o.y = step1(f.y, e.y, p.y, m.y, um.y, st, rst, mn, mx, um.y);
        __stwt(&out_nps[s * B2 + c], o);   // write-through: no L2 dirty-line residency
    }

    if (out_um != nullptr) __stwt(&out_um[c], um);
}

extern "C" void kernel_launch(void* const* d_in, const int* in_sizes, int n_in,
                              void* d_out, int out_size)
{
    const float* fractions     = (const float*)d_in[0];
    const float* exec_samples  = (const float*)d_in[1];
    const float* pos_sizes     = (const float*)d_in[2];
    const float* margin_rates  = (const float*)d_in[3];
    const float* unused_margin = (const float*)d_in[4];
    const float* msm_min       = (const float*)d_in[5];
    const float* msm_step      = (const float*)d_in[6];
    const float* msm_max       = (const float*)d_in[7];

    int B  = in_sizes[4];     // BATCH
    int B2 = B / 2;           // float2 columns

    float* out_nps = (float*)d_out;
    float* out_um  = nullptr;
    if ((long long)out_size >= (long long)N_SYM * B + B)
        out_um = out_nps + (size_t)N_SYM * B;

    int threads = 256;
    int blocks  = (B2 + threads - 1) / threads;   // 256 CTAs for B=131072
    lowlevel_scan_kernel<<<blocks, threads>>>(
        (const float2*)fractions, (const float2*)exec_samples,
        (const float2*)pos_sizes, (const float2*)margin_rates,
        (const float2*)unused_margin,
        msm_min, msm_step, msm_max,
        (float2*)out_nps, (float2*)out_um, B2);
}